// round 12
// baseline (speedup 1.0000x reference)
#include <cuda_runtime.h>
#include <cuda_bf16.h>
#include <stdint.h>
#include <math.h>

#define T_ 64
#define B_ 32
#define V_ 32000
#define H_ 1024
#define K0_ 2560
#define K1_ 2048
#define NBLK 128

// ---------------- device scratch ----------------
__device__ uint4 dW0p[(size_t)4096 * K0_ / 8];
__device__ uint4 dW1p[(size_t)4096 * K1_ / 8];
__device__ uint4 dWkp[(size_t)H_ * H_ / 8];
__device__ uint4 dWc1p[(size_t)H_ * H_ / 8];
__device__ uint4 dWc2p[(size_t)H_ * H_ / 8];
__device__ __nv_bfloat16 dWp[(size_t)V_ * H_];
__device__ float dB0[4096], dB1[4096];
__device__ uint4 dX0p[2][(K0_ / 16) * 64];
__device__ uint4 dX1p[2][(K1_ / 16) * 64];
__device__ uint4 dXcp[(H_ / 16) * 64];
__device__ float dC0[B_ * H_], dC1[B_ * H_];
__device__ float dQ[H_ * B_];
__device__ float dCb1[H_ * B_];
__device__ float dM[(size_t)B_ * H_ * T_];       // [b][j][s] : s contiguous
__device__ __nv_bfloat16 dHBh[(size_t)T_ * B_ * H_];
__device__ float dDist[T_ * T_ * B_];
__device__ __nv_bfloat16 dA[(size_t)T_ * B_ * H_];
__device__ float dMx[T_ * B_], dIs[T_ * B_], dCw[T_ * B_];
__device__ float dLog[(size_t)T_ * B_ * V_];
__device__ int gArr[NBLK * 8];                    // padded flags, stride 8 ints (32B)
__device__ int gRel;

// ---------------- fast transcendentals (FMA pipe) ----------------
__device__ __forceinline__ float fexp(float x) {
    float t = fminf(fmaxf(x * 1.44269504f, -126.0f), 126.0f);
    float r = rintf(t);
    float f = t - r;
    float p = 1.3333558146e-3f;
    p = fmaf(p, f, 9.6181291076e-3f);
    p = fmaf(p, f, 5.5504108664e-2f);
    p = fmaf(p, f, 2.4022650696e-1f);
    p = fmaf(p, f, 6.9314718056e-1f);
    p = fmaf(p, f, 1.0f);
    return p * __int_as_float(((int)r + 127) << 23);
}
__device__ __forceinline__ float flog(float x) {
    int ix = __float_as_int(x);
    int e = (ix >> 23) - 127;
    float m = __int_as_float((ix & 0x7FFFFF) | 0x3F800000);
    if (m > 1.41421356f) { m *= 0.5f; e++; }
    float f = m - 1.0f;
    float z = f * f;
    float p = 7.0376836292e-2f;
    p = fmaf(p, f, -1.1514610310e-1f);
    p = fmaf(p, f, 1.1676998740e-1f);
    p = fmaf(p, f, -1.2420140846e-1f);
    p = fmaf(p, f, 1.4249322787e-1f);
    p = fmaf(p, f, -1.6668057665e-1f);
    p = fmaf(p, f, 2.0000714765e-1f);
    p = fmaf(p, f, -2.4999993993e-1f);
    p = fmaf(p, f, 3.3333331174e-1f);
    float y = fmaf(p * f, z, -0.5f * z) + f;
    return fmaf((float)e, 0.69314718056f, y);
}
__device__ __forceinline__ float fsig(float x) {
    return __fdividef(1.0f, 1.0f + fexp(-x));
}
__device__ __forceinline__ float ftanh(float x) {
    float e = fexp(-2.0f * fabsf(x));
    float t = __fdividef(1.0f - e, 1.0f + e);
    return x >= 0.f ? t : -t;
}

__device__ __forceinline__ int xpk(int n, int k) {
    int p = k >> 4, hi = (k >> 3) & 1, lo = k & 1, ci = (k >> 1) & 3;
    int nh = n >> 4, rh = (n >> 3) & 1, r = n & 7;
    return ((((p * 2 + nh) * 32 + (r * 4 + ci)) * 4) + (rh * 2 + hi)) * 2 + lo;
}

__device__ __forceinline__ float ldcgf(const float* p) {
    float v; asm volatile("ld.global.cg.f32 %0,[%1];" : "=f"(v) : "l"(p)); return v;
}
__device__ __forceinline__ uint4 ldcg4(const void* p) {
    uint4 v;
    asm volatile("ld.global.cg.v4.b32 {%0,%1,%2,%3},[%4];"
                 : "=r"(v.x), "=r"(v.y), "=r"(v.z), "=r"(v.w) : "l"(p));
    return v;
}
__device__ __forceinline__ uint4 ldg4(const void* p) {    // L1-cached, order-pinned
    uint4 v;
    asm volatile("ld.global.v4.b32 {%0,%1,%2,%3},[%4];"
                 : "=r"(v.x), "=r"(v.y), "=r"(v.z), "=r"(v.w) : "l"(p));
    return v;
}
__device__ __forceinline__ void st_rel(int* p, int v) {
    asm volatile("st.release.gpu.global.s32 [%0],%1;" :: "l"(p), "r"(v) : "memory");
}
__device__ __forceinline__ int ld_acq(const int* p) {
    int v; asm volatile("ld.acquire.gpu.global.s32 %0,[%1];" : "=r"(v) : "l"(p) : "memory");
    return v;
}
__device__ __forceinline__ void mma16(float c[4], unsigned a0, unsigned a1,
                                      unsigned a2, unsigned a3, unsigned b0, unsigned b1) {
    asm volatile("mma.sync.aligned.m16n8k16.row.col.f32.bf16.bf16.f32 "
                 "{%0,%1,%2,%3},{%4,%5,%6,%7},{%8,%9},{%0,%1,%2,%3};"
                 : "+f"(c[0]), "+f"(c[1]), "+f"(c[2]), "+f"(c[3])
                 : "r"(a0), "r"(a1), "r"(a2), "r"(a3), "r"(b0), "r"(b1));
}

// ---------------- grid barrier: parallel flag array ----------------
__device__ __forceinline__ void gbar(int e) {
    __syncthreads();
    if (blockIdx.x == 0) {
        if (threadIdx.x == 0) st_rel(&gArr[0], e);
        if (threadIdx.x < NBLK) {
            while (ld_acq(&gArr[threadIdx.x * 8]) < e) { }
        }
        __syncthreads();
        if (threadIdx.x == 0) st_rel(&gRel, e);
    } else {
        if (threadIdx.x == 0) {
            st_rel(&gArr[blockIdx.x * 8], e);
            while (ld_acq(&gRel) < e) { }
        }
        __syncthreads();
    }
    if (blockIdx.x == 0) __syncthreads();   // keep sync counts balanced within block
}

// ---------------- pipelined 32x32xKC GEMM: 16 warps = 8 kseg x 2 nhalf ----------------
template <int KC>
__device__ __forceinline__ void gemm_p(const uint4* __restrict__ Wt,
                                       const uint4* __restrict__ Xp,
                                       float (*G)[32][33]) {
    int tid = threadIdx.x, wid = tid >> 5, lane = tid & 31;
    int ks = wid & 7, nh = wid >> 3;
    constexpr int PPW = KC / 128;
    constexpr int NG = PPW / 2;
    const uint4* Wr = Wt + (size_t)(ks * PPW * 2) * 32 + lane;
    const uint4* Xr = Xp + (size_t)(ks * PPW * 2) * 32 + nh * 32 + lane;
    float c[2][2][4];
#pragma unroll
    for (int i = 0; i < 2; i++)
#pragma unroll
        for (int j = 0; j < 2; j++)
#pragma unroll
            for (int k = 0; k < 4; k++) c[i][j][k] = 0.f;
    uint4 a0[2][2], a1[2][2], xb[2][2];
#pragma unroll
    for (int q = 0; q < 2; q++) {
        a0[0][q] = ldg4(Wr + q * 64);
        a1[0][q] = ldg4(Wr + q * 64 + 32);
        xb[0][q] = ldcg4(Xr + q * 64);
    }
#pragma unroll
    for (int pg = 0; pg < NG; pg++) {
        int cb = pg & 1, nb = cb ^ 1;
        if (pg + 1 < NG) {
#pragma unroll
            for (int q = 0; q < 2; q++) {
                int p = (pg + 1) * 2 + q;
                a0[nb][q] = ldg4(Wr + p * 64);
                a1[nb][q] = ldg4(Wr + p * 64 + 32);
                xb[nb][q] = ldcg4(Xr + p * 64);
            }
        }
#pragma unroll
        for (int q = 0; q < 2; q++) {
            mma16(c[0][0], a0[cb][q].x, a0[cb][q].y, a0[cb][q].z, a0[cb][q].w,
                  xb[cb][q].x, xb[cb][q].y);
            mma16(c[0][1], a0[cb][q].x, a0[cb][q].y, a0[cb][q].z, a0[cb][q].w,
                  xb[cb][q].z, xb[cb][q].w);
            mma16(c[1][0], a1[cb][q].x, a1[cb][q].y, a1[cb][q].z, a1[cb][q].w,
                  xb[cb][q].x, xb[cb][q].y);
            mma16(c[1][1], a1[cb][q].x, a1[cb][q].y, a1[cb][q].z, a1[cb][q].w,
                  xb[cb][q].z, xb[cb][q].w);
        }
    }
    int r = lane >> 2, c2 = (lane & 3) * 2;
#pragma unroll
    for (int mh = 0; mh < 2; mh++)
#pragma unroll
        for (int q = 0; q < 2; q++) {
            int row = mh * 16 + r, col = nh * 16 + q * 8 + c2;
            G[ks][row][col] = c[mh][q][0];
            G[ks][row][col + 1] = c[mh][q][1];
            G[ks][row + 8][col] = c[mh][q][2];
            G[ks][row + 8][col + 1] = c[mh][q][3];
        }
}
__device__ __forceinline__ float gsum(float (*G)[32][33], int row, int b) {
    float s = 0.f;
#pragma unroll
    for (int k = 0; k < 8; k++) s += G[k][row][b];
    return s;
}

// ---------------- persistent decode loop: 512 threads, 4 phases/step ----------------
__global__ void __launch_bounds__(512, 1)
decode_loop(const int* __restrict__ tok, const float* __restrict__ Eb,
            const float* __restrict__ bk, const float* __restrict__ bc) {
    __shared__ __align__(16) float Gs[8][32][33];
    int bid = blockIdx.x, tid = threadIdx.x;
    int b = tid & 31;
    int e = 0;
    const uint4* W0t = dW0p + (size_t)bid * (160 * 64);
    const uint4* W1t = dW1p + (size_t)bid * (128 * 64);

    for (int t = 0; t < T_; t++) {
        int cur = t & 1, nxt = cur ^ 1;

        // ---- Phase A: layer-0 GEMM + LSTM pointwise ----
        gemm_p<K0_>(W0t, dX0p[cur], Gs);
        __syncthreads();
        if (tid < 256) {
            int hl = tid >> 5;
            int h = bid * 8 + hl, j0 = bid * 32 + hl * 4;
            float g0 = gsum(Gs, hl * 4 + 0, b) + dB0[j0 + 0];
            float g1 = gsum(Gs, hl * 4 + 1, b) + dB0[j0 + 1];
            float g2 = gsum(Gs, hl * 4 + 2, b) + dB0[j0 + 2];
            float g3 = gsum(Gs, hl * 4 + 3, b) + dB0[j0 + 3];
            float c = dC0[h * 32 + b];
            float cn = fsig(g1) * c + fsig(g0) * ftanh(g2);
            float hn = fsig(g3) * ftanh(cn);
            dC0[h * 32 + b] = cn;
            __nv_bfloat16 hb = __float2bfloat16(hn);
            ((__nv_bfloat16*)dX1p[cur])[xpk(b, h)] = hb;
            ((__nv_bfloat16*)dX0p[nxt])[xpk(b, 1536 + h)] = hb;
        }
        gbar(++e);

        // ---- Phase B: layer-1 GEMM + LSTM pointwise ----
        gemm_p<K1_>(W1t, dX1p[cur], Gs);
        __syncthreads();
        if (tid < 256) {
            int hl = tid >> 5;
            int h = bid * 8 + hl, j0 = bid * 32 + hl * 4;
            float g0 = gsum(Gs, hl * 4 + 0, b) + dB1[j0 + 0];
            float g1 = gsum(Gs, hl * 4 + 1, b) + dB1[j0 + 1];
            float g2 = gsum(Gs, hl * 4 + 2, b) + dB1[j0 + 2];
            float g3 = gsum(Gs, hl * 4 + 3, b) + dB1[j0 + 3];
            float c = dC1[h * 32 + b];
            float cn = fsig(g1) * c + fsig(g0) * ftanh(g2);
            float hn = fsig(g3) * ftanh(cn);
            dC1[h * 32 + b] = cn;
            __nv_bfloat16 hb = __float2bfloat16(hn);
            ((__nv_bfloat16*)dXcp)[xpk(b, h)] = hb;
            ((__nv_bfloat16*)dX1p[nxt])[xpk(b, 1024 + h)] = hb;
            dHBh[((size_t)t * 32 + b) * H_ + h] = hb;
        }
        gbar(++e);

        // ---- Phase C: q/M/comb1 GEMMs + emb prefetch ----
        if (bid < 32) {
            gemm_p<H_>(dWkp + (size_t)bid * 4096, dXcp, Gs);
            __syncthreads();
            int rl = tid >> 5;
            dQ[(bid * 32 + rl) * 32 + b] = gsum(Gs, rl, b);
            dQ[(bid * 32 + rl + 16) * 32 + b] = gsum(Gs, rl + 16, b);
        } else if (bid < 64) {
            int jt = bid - 32;
            gemm_p<H_>(dWc2p + (size_t)jt * 4096, dXcp, Gs);
            __syncthreads();
            int rl = tid >> 5;
            // dM layout [b][j][s]
            dM[((size_t)b * H_ + jt * 32 + rl) * T_ + t] = gsum(Gs, rl, b);
            dM[((size_t)b * H_ + jt * 32 + rl + 16) * T_ + t] = gsum(Gs, rl + 16, b);
        } else if (bid < 96) {
            int jt = bid - 64;
            gemm_p<H_>(dWc1p + (size_t)jt * 4096, dXcp, Gs);
            __syncthreads();
            int rl = tid >> 5;
            dCb1[(jt * 32 + rl) * 32 + b] = gsum(Gs, rl, b);
            dCb1[(jt * 32 + rl + 16) * 32 + b] = gsum(Gs, rl + 16, b);
        } else if (t + 1 < T_) {
            int bb = bid - 96;
            int tk = tok[(t + 1) * 32 + bb];
            if (tid < 512)
                ((__nv_bfloat16*)dX0p[nxt])[xpk(bb, tid)] =
                    __float2bfloat16(Eb[(size_t)tk * 512 + tid]);
        }
        gbar(++e);

        // ---- Phase D: attention + comb finalize (32 blocks, 512 threads) ----
        if (bid < 32) {
            int bb = bid;
            float* qv = (float*)Gs;          // 1024
            float* sc = qv + 1024;           // 64
            float* red = sc + 64;            // 512
            int h2 = tid * 2;
            {
                qv[h2] = ldcgf(&dQ[h2 * 32 + bb]);
                qv[h2 + 1] = ldcgf(&dQ[(h2 + 1) * 32 + bb]);
                const __nv_bfloat16* ht = &dHBh[((size_t)t * 32 + bb) * H_ + h2];
                red[tid] = __bfloat162float(ht[0]) * bk[h2]
                         + __bfloat162float(ht[1]) * bk[h2 + 1];
            }
            __syncthreads();
            for (int st = 256; st; st >>= 1) { if (tid < st) red[tid] += red[tid + st]; __syncthreads(); }
            float bkh = red[0];
            __syncthreads();
            int w = tid >> 5, lane = tid & 31;
            for (int si = w; si <= t; si += 16) {
                const __nv_bfloat16* hr = &dHBh[((size_t)si * 32 + bb) * H_];
                float acc = 0.f;
                for (int h = lane * 8; h < H_; h += 256) {
                    uint4 hv = *(const uint4*)(hr + h);
                    float2 a0 = __bfloat1622float2(*(__nv_bfloat162*)&hv.x);
                    float2 a1 = __bfloat1622float2(*(__nv_bfloat162*)&hv.y);
                    float2 a2 = __bfloat1622float2(*(__nv_bfloat162*)&hv.z);
                    float2 a3 = __bfloat1622float2(*(__nv_bfloat162*)&hv.w);
                    acc += a0.x * qv[h] + a0.y * qv[h + 1] + a1.x * qv[h + 2] + a1.y * qv[h + 3]
                         + a2.x * qv[h + 4] + a2.y * qv[h + 5] + a3.x * qv[h + 6] + a3.y * qv[h + 7];
                }
#pragma unroll
                for (int o = 16; o; o >>= 1) acc += __shfl_xor_sync(0xffffffffu, acc, o);
                if (!lane) {
                    float v = acc + bkh;
                    if (tok[si * 32 + bb] == 0) v += -99999.0f;
                    sc[si] = v;
                }
            }
            __syncthreads();
            float v = (tid < 64 && tid <= t) ? sc[tid] : -1e30f;
            red[tid] = v; __syncthreads();
            for (int st = 256; st; st >>= 1) { if (tid < st) red[tid] = fmaxf(red[tid], red[tid + st]); __syncthreads(); }
            float m = red[0]; __syncthreads();
            float ev = (tid < 64 && tid <= t) ? fexp(v - m) : 0.f;
            red[tid] = ev; __syncthreads();
            for (int st = 256; st; st >>= 1) { if (tid < st) red[tid] += red[tid + st]; __syncthreads(); }
            float inv = 1.0f / red[0];
            if (tid < 64) sc[tid] = (tid <= t) ? ev * inv : 0.f;
            __syncthreads();
            if (tid < 64) dDist[(t * T_ + tid) * 32 + bb] = sc[tid];
            {
                int j = tid * 2;
                float a0 = ldcgf(&dCb1[(j + 0) * 32 + bb]);
                float a1 = ldcgf(&dCb1[(j + 1) * 32 + bb]);
                const float* M0 = &dM[((size_t)bb * H_ + j) * T_];       // 64 contiguous
                const float* M1 = M0 + T_;
                // chunks of 4 s-values; sc[s]=0 beyond t zeroes the padding
                for (int s4 = 0; s4 <= t; s4 += 4) {
                    uint4 u0 = ldcg4(M0 + s4);
                    uint4 u1 = ldcg4(M1 + s4);
                    float4 m0 = *(float4*)&u0;
                    float4 m1 = *(float4*)&u1;
                    float d0 = sc[s4], d1 = sc[s4 + 1], d2 = sc[s4 + 2], d3 = sc[s4 + 3];
                    a0 = fmaf(d0, m0.x, a0); a1 = fmaf(d0, m1.x, a1);
                    a0 = fmaf(d1, m0.y, a0); a1 = fmaf(d1, m1.y, a1);
                    a0 = fmaf(d2, m0.z, a0); a1 = fmaf(d2, m1.z, a1);
                    a0 = fmaf(d3, m0.w, a0); a1 = fmaf(d3, m1.w, a1);
                }
                a0 += bc[j]; a1 += bc[j + 1];
                __nv_bfloat162 p0 = __floats2bfloat162_rn(a0, a1);
                ((unsigned*)dX0p[nxt])[xpk(bb, 512 + j) >> 1] = *(unsigned*)&p0;
                *(unsigned*)&dA[((size_t)t * 32 + bb) * H_ + j] = *(unsigned*)&p0;
            }
        }
        gbar(++e);
    }
}

// ---------------- prep kernel 0: pack W0 + W1 ----------------
__global__ void pk_big(const float* __restrict__ Wih0, const float* __restrict__ Whh0,
                       const float* __restrict__ Wih1, const float* __restrict__ Whh1) {
    const size_t N0 = (size_t)4096 * K0_ / 8;
    const size_t N1 = (size_t)4096 * K1_ / 8;
    for (size_t uu = (size_t)blockIdx.x * blockDim.x + threadIdx.x; uu < N0 + N1;
         uu += (size_t)gridDim.x * blockDim.x) {
        bool first = uu < N0;
        size_t u = first ? uu : uu - N0;
        int PAN = first ? 160 : 128;
        const float* Wih = first ? Wih0 : Wih1;
        const float* Whh = first ? Whh0 : Whh1;
        int KIH = first ? 1536 : 1024;
        int lane = (int)(u & 31); size_t t1 = u >> 5; int mh = (int)(t1 & 1); size_t t2 = t1 >> 1;
        int p = (int)(t2 % PAN); int jt = (int)(t2 / PAN);
        int r = lane >> 2, ci = lane & 3;
        unsigned o[4];
#pragma unroll
        for (int reg = 0; reg < 4; reg++) {
            int rh = reg & 1, hi = reg >> 1;
            int row = jt * 32 + mh * 16 + rh * 8 + r;
            int orow = (row & 3) * 1024 + (row >> 2);
            int col = p * 16 + hi * 8 + ci * 2;
            float v0, v1;
            if (col < KIH) { v0 = Wih[(size_t)orow * KIH + col]; v1 = Wih[(size_t)orow * KIH + col + 1]; }
            else { v0 = Whh[(size_t)orow * 1024 + col - KIH]; v1 = Whh[(size_t)orow * 1024 + col - KIH + 1]; }
            __nv_bfloat162 bb = __floats2bfloat162_rn(v0, v1);
            o[reg] = *(unsigned*)&bb;
        }
        if (first) dW0p[u] = make_uint4(o[0], o[1], o[2], o[3]);
        else dW1p[u] = make_uint4(o[0], o[1], o[2], o[3]);
    }
}

// ---------------- prep kernel 1: pack Wk^T/Wc1/Wc2 + cast Wp ----------------
__global__ void pk_small(const float* __restrict__ Wk, const float* __restrict__ Wc,
                         const float* __restrict__ Wp) {
    const size_t NP = (size_t)H_ * H_ / 8;
    const size_t NW = (size_t)V_ * H_ / 8;
    for (size_t uu = (size_t)blockIdx.x * blockDim.x + threadIdx.x; uu < 3 * NP + NW;
         uu += (size_t)gridDim.x * blockDim.x) {
        if (uu < 3 * NP) {
            int which = (int)(uu / NP);
            size_t rem = uu % NP;
            int lane = (int)(rem & 31); size_t t1 = rem >> 5; int mh = (int)(t1 & 1); size_t t2 = t1 >> 1;
            int p = (int)(t2 % 64); int jt = (int)(t2 / 64);
            int r = lane >> 2, ci = lane & 3;
            unsigned o[4];
#pragma unroll
            for (int reg = 0; reg < 4; reg++) {
                int rh = reg & 1, hi = reg >> 1;
                int row = jt * 32 + mh * 16 + rh * 8 + r;
                int col = p * 16 + hi * 8 + ci * 2;
                float v0, v1;
                if (which == 0) { v0 = Wk[(size_t)col * 1024 + row]; v1 = Wk[(size_t)(col + 1) * 1024 + row]; }
                else if (which == 1) { v0 = Wc[(size_t)row * 2048 + col]; v1 = Wc[(size_t)row * 2048 + col + 1]; }
                else { v0 = Wc[(size_t)row * 2048 + 1024 + col]; v1 = Wc[(size_t)row * 2048 + 1025 + col]; }
                __nv_bfloat162 bb = __floats2bfloat162_rn(v0, v1);
                o[reg] = *(unsigned*)&bb;
            }
            if (which == 0) dWkp[rem] = make_uint4(o[0], o[1], o[2], o[3]);
            else if (which == 1) dWc1p[rem] = make_uint4(o[0], o[1], o[2], o[3]);
            else dWc2p[rem] = make_uint4(o[0], o[1], o[2], o[3]);
        } else {
            size_t w = uu - 3 * NP;
            float4 f0 = *(const float4*)(Wp + w * 8);
            float4 f1 = *(const float4*)(Wp + w * 8 + 4);
            __nv_bfloat162 b0 = __floats2bfloat162_rn(f0.x, f0.y);
            __nv_bfloat162 b1 = __floats2bfloat162_rn(f0.z, f0.w);
            __nv_bfloat162 b2 = __floats2bfloat162_rn(f1.x, f1.y);
            __nv_bfloat162 b3 = __floats2bfloat162_rn(f1.z, f1.w);
            ((uint4*)dWp)[w] = make_uint4(*(unsigned*)&b0, *(unsigned*)&b1,
                                          *(unsigned*)&b2, *(unsigned*)&b3);
        }
    }
}

// ---------------- prep kernel 2: state init ----------------
__global__ void pk_state(const float* __restrict__ bih0, const float* __restrict__ bhh0,
                         const float* __restrict__ bih1, const float* __restrict__ bhh1,
                         const float* __restrict__ h0, const float* __restrict__ c0,
                         const float* __restrict__ Eb, const int* __restrict__ tok) {
    int i = blockIdx.x * blockDim.x + threadIdx.x;   // 32768 threads
    int bb = i >> 10, h = i & 1023;
    dC0[h * 32 + bb] = c0[(size_t)bb * H_ + h];
    dC1[h * 32 + bb] = c0[(size_t)B_ * H_ + (size_t)bb * H_ + h];
    ((__nv_bfloat16*)dX0p[0])[xpk(bb, 1536 + h)] = __float2bfloat16(h0[(size_t)bb * H_ + h]);
    ((__nv_bfloat16*)dX1p[0])[xpk(bb, 1024 + h)] =
        __float2bfloat16(h0[(size_t)B_ * H_ + (size_t)bb * H_ + h]);
    ((__nv_bfloat16*)dX0p[0])[xpk(bb, 512 + h)] = __float2bfloat16(0.0f);
    if (i < 4096) {
        int h2 = i >> 2, g = i & 3;
        dB0[i] = bih0[g * 1024 + h2] + bhh0[g * 1024 + h2];
        dB1[i] = bih1[g * 1024 + h2] + bhh1[g * 1024 + h2];
    }
    if (i < 32 * 512) {
        int b2 = i >> 9, e2 = i & 511;
        ((__nv_bfloat16*)dX0p[0])[xpk(b2, e2)] = __float2bfloat16(Eb[(size_t)tok[b2] * 512 + e2]);
    }
    if (i < NBLK) gArr[i * 8] = 0;
    if (i == 0) gRel = 0;
}

// ---------------- logits GEMM: 128x128 double-buffered ----------------
__global__ void __launch_bounds__(256) gemm_logits(const float* __restrict__ bp) {
    int v0 = blockIdx.x * 128, r0 = blockIdx.y * 128;
    __shared__ __nv_bfloat16 As[2][128][24];
    __shared__ __nv_bfloat16 Bs[2][128][24];
    int tid = threadIdx.x, wid = tid >> 5, lane = tid & 31;
    int mh = wid >> 2, nq = wid & 3;
    int r = lane >> 2, c2 = (lane & 3) * 2;
    int lrow = tid >> 1, lseg = (tid & 1) * 8;
    float acc[4][4][4];
#pragma unroll
    for (int a = 0; a < 4; a++)
#pragma unroll
        for (int bb = 0; bb < 4; bb++)
#pragma unroll
            for (int c = 0; c < 4; c++) acc[a][bb][c] = 0.f;

    *(uint4*)&As[0][lrow][lseg] = *(const uint4*)&dA[(size_t)(r0 + lrow) * H_ + lseg];
    *(uint4*)&Bs[0][lrow][lseg] = *(const uint4*)&dWp[(size_t)(v0 + lrow) * H_ + lseg];
    for (int ks = 0; ks < 64; ks++) {
        __syncthreads();
        uint4 na, nb;
        if (ks < 63) {
            na = *(const uint4*)&dA[(size_t)(r0 + lrow) * H_ + (ks + 1) * 16 + lseg];
            nb = *(const uint4*)&dWp[(size_t)(v0 + lrow) * H_ + (ks + 1) * 16 + lseg];
        }
        int cur = ks & 1;
#pragma unroll
        for (int mi = 0; mi < 4; mi++) {
            int row = mh * 64 + mi * 16;
            unsigned a0 = *(unsigned*)&As[cur][row + r][c2];
            unsigned a1 = *(unsigned*)&As[cur][row + r + 8][c2];
            unsigned a2 = *(unsigned*)&As[cur][row + r][c2 + 8];
            unsigned a3 = *(unsigned*)&As[cur][row + r + 8][c2 + 8];
#pragma unroll
            for (int ni = 0; ni < 4; ni++) {
                int n = nq * 32 + ni * 8 + r;
                unsigned b0 = *(unsigned*)&Bs[cur][n][c2];
                unsigned b1 = *(unsigned*)&Bs[cur][n][c2 + 8];
                mma16(acc[mi][ni], a0, a1, a2, a3, b0, b1);
            }
        }
        if (ks < 63) {
            *(uint4*)&As[cur ^ 1][lrow][lseg] = na;
            *(uint4*)&Bs[cur ^ 1][lrow][lseg] = nb;
        }
    }
#pragma unroll
    for (int mi = 0; mi < 4; mi++) {
        int row = r0 + mh * 64 + mi * 16 + r;
#pragma unroll
        for (int ni = 0; ni < 4; ni++) {
            int col = v0 + nq * 32 + ni * 8 + c2;
            float b0 = bp[col], b1 = bp[col + 1];
            dLog[(size_t)row * V_ + col] = acc[mi][ni][0] + b0;
            dLog[(size_t)row * V_ + col + 1] = acc[mi][ni][1] + b1;
            dLog[(size_t)(row + 8) * V_ + col] = acc[mi][ni][2] + b0;
            dLog[(size_t)(row + 8) * V_ + col + 1] = acc[mi][ni][3] + b1;
        }
    }
}

// ---------------- softmax + mixture log output ----------------
__global__ void softmax_out(float* __restrict__ out) {
    int rr = blockIdx.x, tid = threadIdx.x;
    const float* L = dLog + (size_t)rr * V_;
    __shared__ float rm[256], rs[256];
    float m = -1e30f, s = 0.f;
    for (int v = tid; v < V_; v += 256) {
        float x = L[v];
        if (x > m) { s = fmaf(s, fexp(m - x), 1.0f); m = x; }
        else s += fexp(x - m);
    }
    rm[tid] = m; rs[tid] = s; __syncthreads();
    for (int st = 128; st; st >>= 1) {
        if (tid < st) {
            float m2 = rm[tid + st], s2 = rs[tid + st];
            float M = fmaxf(rm[tid], m2);
            rs[tid] = rs[tid] * fexp(rm[tid] - M) + s2 * fexp(m2 - M);
            rm[tid] = M;
        }
        __syncthreads();
    }
    m = rm[0];
    float inv = 1.0f / rs[0];
    float cw = fexp(L[3] - m) * inv;          // COPY_ID = 3
    if (tid == 0) { dMx[rr] = m; dIs[rr] = inv; dCw[rr] = cw; }
    float ce = cw * 1e-7f, oc = (1.0f - cw) * inv;
    float* O = out + (size_t)rr * V_;
    for (int v = tid; v < V_; v += 256)
        O[v] = flog(fmaf(oc, fexp(L[v] - m), ce));
}

__global__ void fixup(float* __restrict__ out, const int* __restrict__ tok) {
    int rr = blockIdx.x;
    int t = rr >> 5, b = rr & 31;
    int s = threadIdx.x;
    __shared__ int tk[T_];
    __shared__ float dd[T_];
    tk[s] = tok[s * 32 + b];
    dd[s] = dDist[(t * T_ + s) * 32 + b];
    __syncthreads();
    int mytok = tk[s];
    float tot = 0.f;
    for (int s2 = 0; s2 < T_; s2++) if (tk[s2] == mytok) tot += dd[s2];
    float m = dMx[rr], inv = dIs[rr], cw = dCw[rr];
    float p = fexp(dLog[(size_t)rr * V_ + mytok] - m) * inv;
    out[(size_t)rr * V_ + mytok] = flog(cw * (1e-7f + tot) + (1.0f - cw) * p);
}

// ---------------- host ----------------
extern "C" void kernel_launch(void* const* d_in, const int* in_sizes, int n_in,
                              void* d_out, int out_size) {
    const int* tok = (const int*)d_in[0];
    const float* h0 = (const float*)d_in[1];
    const float* c0 = (const float*)d_in[2];
    const float* Eb = (const float*)d_in[3];
    const float* Wih0 = (const float*)d_in[4];
    const float* Whh0 = (const float*)d_in[5];
    const float* bih0 = (const float*)d_in[6];
    const float* bhh0 = (const float*)d_in[7];
    const float* Wih1 = (const float*)d_in[8];
    const float* Whh1 = (const float*)d_in[9];
    const float* bih1 = (const float*)d_in[10];
    const float* bhh1 = (const float*)d_in[11];
    const float* Wk = (const float*)d_in[12];
    const float* bk = (const float*)d_in[13];
    const float* Wc = (const float*)d_in[14];
    const float* bc = (const float*)d_in[15];
    const float* Wp = (const float*)d_in[16];
    const float* bp = (const float*)d_in[17];
    float* out = (float*)d_out;

    pk_big<<<4096, 256>>>(Wih0, Whh0, Wih1, Whh1);           // launch 0
    pk_small<<<4096, 256>>>(Wk, Wc, Wp);                     // launch 1
    pk_state<<<128, 256>>>(bih0, bhh0, bih1, bhh1, h0, c0, Eb, tok);  // launch 2
    decode_loop<<<NBLK, 512>>>(tok, Eb, bk, bc);             // launch 3 (profiled)
    gemm_logits<<<dim3(V_ / 128, (T_ * B_) / 128), 256>>>(bp);
    softmax_out<<<T_ * B_, 256>>>(out);
    fixup<<<T_ * B_, 64>>>(out, tok);
}

// round 16
// speedup vs baseline: 1.0053x; 1.0053x over previous
#include <cuda_runtime.h>
#include <cuda_bf16.h>
#include <cuda_fp8.h>
#include <stdint.h>
#include <math.h>

#define T_ 64
#define B_ 32
#define V_ 32000
#define H_ 1024
#define K0_ 2560
#define K1_ 2048
#define NBLK 128

// ---------------- device scratch ----------------
__device__ uint4 dW0p[(size_t)4096 * K0_ / 16];   // fp8 packed: [tile][p(K/32)][mh][lane]
__device__ uint4 dW1p[(size_t)4096 * K1_ / 16];
__device__ uint4 dWkp[(size_t)H_ * H_ / 8];       // bf16 packed
__device__ uint4 dWc1p[(size_t)H_ * H_ / 8];
__device__ uint4 dWc2p[(size_t)H_ * H_ / 8];
__device__ __nv_bfloat16 dWp[(size_t)V_ * H_];
__device__ float dB0[4096], dB1[4096];
__device__ uint4 dX0p[2][(K0_ / 32) * 64];        // fp8 packed activations
__device__ uint4 dX1p[2][(K1_ / 32) * 64];
__device__ uint4 dXcp[(H_ / 16) * 64];            // bf16 packed htop
__device__ float dC0[B_ * H_], dC1[B_ * H_];
__device__ float dQ[H_ * B_];
__device__ float dCb1[H_ * B_];
__device__ float dM[(size_t)B_ * H_ * T_];        // [b][j][s]
__device__ __nv_bfloat16 dHBh[(size_t)T_ * B_ * H_];
__device__ float dDist[T_ * T_ * B_];
__device__ __nv_bfloat16 dA[(size_t)T_ * B_ * H_];
__device__ float dMx[T_ * B_], dIs[T_ * B_], dCw[T_ * B_];
__device__ float dLog[(size_t)T_ * B_ * V_];
__device__ int gCnt;
__device__ int gRel;

// ---------------- fast transcendentals (FMA pipe) ----------------
__device__ __forceinline__ float fexp(float x) {
    float t = fminf(fmaxf(x * 1.44269504f, -126.0f), 126.0f);
    float r = rintf(t);
    float f = t - r;
    float p = 1.3333558146e-3f;
    p = fmaf(p, f, 9.6181291076e-3f);
    p = fmaf(p, f, 5.5504108664e-2f);
    p = fmaf(p, f, 2.4022650696e-1f);
    p = fmaf(p, f, 6.9314718056e-1f);
    p = fmaf(p, f, 1.0f);
    return p * __int_as_float(((int)r + 127) << 23);
}
__device__ __forceinline__ float flog(float x) {
    int ix = __float_as_int(x);
    int e = (ix >> 23) - 127;
    float m = __int_as_float((ix & 0x7FFFFF) | 0x3F800000);
    if (m > 1.41421356f) { m *= 0.5f; e++; }
    float f = m - 1.0f;
    float z = f * f;
    float p = 7.0376836292e-2f;
    p = fmaf(p, f, -1.1514610310e-1f);
    p = fmaf(p, f, 1.1676998740e-1f);
    p = fmaf(p, f, -1.2420140846e-1f);
    p = fmaf(p, f, 1.4249322787e-1f);
    p = fmaf(p, f, -1.6668057665e-1f);
    p = fmaf(p, f, 2.0000714765e-1f);
    p = fmaf(p, f, -2.4999993993e-1f);
    p = fmaf(p, f, 3.3333331174e-1f);
    float y = fmaf(p * f, z, -0.5f * z) + f;
    return fmaf((float)e, 0.69314718056f, y);
}
__device__ __forceinline__ float fsig(float x) {
    return __fdividef(1.0f, 1.0f + fexp(-x));
}
__device__ __forceinline__ float ftanh(float x) {
    float e = fexp(-2.0f * fabsf(x));
    float t = __fdividef(1.0f - e, 1.0f + e);
    return x >= 0.f ? t : -t;
}

// bf16 packed-X index (phase C operand)
__device__ __forceinline__ int xpk(int n, int k) {
    int p = k >> 4, hi = (k >> 3) & 1, lo = k & 1, ci = (k >> 1) & 3;
    int nh = n >> 4, rh = (n >> 3) & 1, r = n & 7;
    return ((((p * 2 + nh) * 32 + (r * 4 + ci)) * 4) + (rh * 2 + hi)) * 2 + lo;
}
// fp8 packed-X byte index (k-panels of 32)
__device__ __forceinline__ int xpk8(int n, int k) {
    int p = k >> 5, hi = (k >> 4) & 1, ci = (k >> 2) & 3, lo = k & 3;
    int nh = n >> 4, nf = (n >> 3) & 1, r = n & 7;
    return (((p * 2 + nh) * 32 + (r * 4 + ci)) * 4 + (nf * 2 + hi)) * 4 + lo;
}
__device__ __forceinline__ unsigned char f2e4m3(float v) {
    return (unsigned char)__nv_cvt_float_to_fp8(v, __NV_SATFINITE, __NV_E4M3);
}

__device__ __forceinline__ float ldcgf(const float* p) {
    float v; asm volatile("ld.global.cg.f32 %0,[%1];" : "=f"(v) : "l"(p)); return v;
}
__device__ __forceinline__ uint4 ldcg4(const void* p) {
    uint4 v;
    asm volatile("ld.global.cg.v4.b32 {%0,%1,%2,%3},[%4];"
                 : "=r"(v.x), "=r"(v.y), "=r"(v.z), "=r"(v.w) : "l"(p));
    return v;
}
__device__ __forceinline__ uint4 ldg4(const void* p) {    // L1-cached, order-pinned
    uint4 v;
    asm volatile("ld.global.v4.b32 {%0,%1,%2,%3},[%4];"
                 : "=r"(v.x), "=r"(v.y), "=r"(v.z), "=r"(v.w) : "l"(p));
    return v;
}
__device__ __forceinline__ void st_rel(int* p, int v) {
    asm volatile("st.release.gpu.global.s32 [%0],%1;" :: "l"(p), "r"(v) : "memory");
}
__device__ __forceinline__ int ld_acq(const int* p) {
    int v; asm volatile("ld.acquire.gpu.global.s32 %0,[%1];" : "=r"(v) : "l"(p) : "memory");
    return v;
}
__device__ __forceinline__ int atom_add_rel(int* p, int v) {
    int old;
    asm volatile("atom.release.gpu.global.add.s32 %0,[%1],%2;"
                 : "=r"(old) : "l"(p), "r"(v) : "memory");
    return old;
}
__device__ __forceinline__ void mma16(float c[4], unsigned a0, unsigned a1,
                                      unsigned a2, unsigned a3, unsigned b0, unsigned b1) {
    asm volatile("mma.sync.aligned.m16n8k16.row.col.f32.bf16.bf16.f32 "
                 "{%0,%1,%2,%3},{%4,%5,%6,%7},{%8,%9},{%0,%1,%2,%3};"
                 : "+f"(c[0]), "+f"(c[1]), "+f"(c[2]), "+f"(c[3])
                 : "r"(a0), "r"(a1), "r"(a2), "r"(a3), "r"(b0), "r"(b1));
}
__device__ __forceinline__ void mma32f(float c[4], unsigned a0, unsigned a1,
                                       unsigned a2, unsigned a3, unsigned b0, unsigned b1) {
    asm volatile("mma.sync.aligned.m16n8k32.row.col.f32.e4m3.e4m3.f32 "
                 "{%0,%1,%2,%3},{%4,%5,%6,%7},{%8,%9},{%0,%1,%2,%3};"
                 : "+f"(c[0]), "+f"(c[1]), "+f"(c[2]), "+f"(c[3])
                 : "r"(a0), "r"(a1), "r"(a2), "r"(a3), "r"(b0), "r"(b1));
}

// ---------------- grid barrier: atomic arrival (round-11 proven) ----------------
__device__ __forceinline__ void gbar(int e) {
    __syncthreads();
    if (threadIdx.x == 0) {
        int v = atom_add_rel(&gCnt, 1);
        if (v == e * NBLK - 1) st_rel(&gRel, e);
        else while (ld_acq(&gRel) < e) { }
    }
    __syncthreads();
}

// ---------------- fp8 pipelined 32x32xKC GEMM (phases A/B) ----------------
// 16 warps = 8 kseg x 2 nhalf; k-panels of 32; identical pipeline structure.
template <int KC>
__device__ __forceinline__ void gemm_p8(const uint4* __restrict__ Wt,
                                        const uint4* __restrict__ Xp,
                                        float (*G)[32][33]) {
    int tid = threadIdx.x, wid = tid >> 5, lane = tid & 31;
    int ks = wid & 7, nh = wid >> 3;
    constexpr int PPW = KC / 256;          // k32 panels per kseg (10 / 8)
    constexpr int NG = PPW / 2;
    const uint4* Wr = Wt + (size_t)(ks * PPW * 2) * 32 + lane;
    const uint4* Xr = Xp + (size_t)(ks * PPW * 2) * 32 + nh * 32 + lane;
    float c[2][2][4];
#pragma unroll
    for (int i = 0; i < 2; i++)
#pragma unroll
        for (int j = 0; j < 2; j++)
#pragma unroll
            for (int k = 0; k < 4; k++) c[i][j][k] = 0.f;
    uint4 a0[2][2], a1[2][2], xb[2][2];
#pragma unroll
    for (int q = 0; q < 2; q++) {
        a0[0][q] = ldg4(Wr + q * 64);
        a1[0][q] = ldg4(Wr + q * 64 + 32);
        xb[0][q] = ldcg4(Xr + q * 64);
    }
#pragma unroll
    for (int pg = 0; pg < NG; pg++) {
        int cb = pg & 1, nb = cb ^ 1;
        if (pg + 1 < NG) {
#pragma unroll
            for (int q = 0; q < 2; q++) {
                int p = (pg + 1) * 2 + q;
                a0[nb][q] = ldg4(Wr + p * 64);
                a1[nb][q] = ldg4(Wr + p * 64 + 32);
                xb[nb][q] = ldcg4(Xr + p * 64);
            }
        }
#pragma unroll
        for (int q = 0; q < 2; q++) {
            mma32f(c[0][0], a0[cb][q].x, a0[cb][q].y, a0[cb][q].z, a0[cb][q].w,
                   xb[cb][q].x, xb[cb][q].y);
            mma32f(c[0][1], a0[cb][q].x, a0[cb][q].y, a0[cb][q].z, a0[cb][q].w,
                   xb[cb][q].z, xb[cb][q].w);
            mma32f(c[1][0], a1[cb][q].x, a1[cb][q].y, a1[cb][q].z, a1[cb][q].w,
                   xb[cb][q].x, xb[cb][q].y);
            mma32f(c[1][1], a1[cb][q].x, a1[cb][q].y, a1[cb][q].z, a1[cb][q].w,
                   xb[cb][q].z, xb[cb][q].w);
        }
    }
    int r = lane >> 2, c2 = (lane & 3) * 2;
#pragma unroll
    for (int mh = 0; mh < 2; mh++)
#pragma unroll
        for (int q = 0; q < 2; q++) {
            int row = mh * 16 + r, col = nh * 16 + q * 8 + c2;
            G[ks][row][col] = c[mh][q][0];
            G[ks][row][col + 1] = c[mh][q][1];
            G[ks][row + 8][col] = c[mh][q][2];
            G[ks][row + 8][col + 1] = c[mh][q][3];
        }
}

// ---------------- bf16 pipelined GEMM (phase C) ----------------
template <int KC>
__device__ __forceinline__ void gemm_p(const uint4* __restrict__ Wt,
                                       const uint4* __restrict__ Xp,
                                       float (*G)[32][33]) {
    int tid = threadIdx.x, wid = tid >> 5, lane = tid & 31;
    int ks = wid & 7, nh = wid >> 3;
    constexpr int PPW = KC / 128;
    constexpr int NG = PPW / 2;
    const uint4* Wr = Wt + (size_t)(ks * PPW * 2) * 32 + lane;
    const uint4* Xr = Xp + (size_t)(ks * PPW * 2) * 32 + nh * 32 + lane;
    float c[2][2][4];
#pragma unroll
    for (int i = 0; i < 2; i++)
#pragma unroll
        for (int j = 0; j < 2; j++)
#pragma unroll
            for (int k = 0; k < 4; k++) c[i][j][k] = 0.f;
    uint4 a0[2][2], a1[2][2], xb[2][2];
#pragma unroll
    for (int q = 0; q < 2; q++) {
        a0[0][q] = ldg4(Wr + q * 64);
        a1[0][q] = ldg4(Wr + q * 64 + 32);
        xb[0][q] = ldcg4(Xr + q * 64);
    }
#pragma unroll
    for (int pg = 0; pg < NG; pg++) {
        int cb = pg & 1, nb = cb ^ 1;
        if (pg + 1 < NG) {
#pragma unroll
            for (int q = 0; q < 2; q++) {
                int p = (pg + 1) * 2 + q;
                a0[nb][q] = ldg4(Wr + p * 64);
                a1[nb][q] = ldg4(Wr + p * 64 + 32);
                xb[nb][q] = ldcg4(Xr + p * 64);
            }
        }
#pragma unroll
        for (int q = 0; q < 2; q++) {
            mma16(c[0][0], a0[cb][q].x, a0[cb][q].y, a0[cb][q].z, a0[cb][q].w,
                  xb[cb][q].x, xb[cb][q].y);
            mma16(c[0][1], a0[cb][q].x, a0[cb][q].y, a0[cb][q].z, a0[cb][q].w,
                  xb[cb][q].z, xb[cb][q].w);
            mma16(c[1][0], a1[cb][q].x, a1[cb][q].y, a1[cb][q].z, a1[cb][q].w,
                  xb[cb][q].x, xb[cb][q].y);
            mma16(c[1][1], a1[cb][q].x, a1[cb][q].y, a1[cb][q].z, a1[cb][q].w,
                  xb[cb][q].z, xb[cb][q].w);
        }
    }
    int r = lane >> 2, c2 = (lane & 3) * 2;
#pragma unroll
    for (int mh = 0; mh < 2; mh++)
#pragma unroll
        for (int q = 0; q < 2; q++) {
            int row = mh * 16 + r, col = nh * 16 + q * 8 + c2;
            G[ks][row][col] = c[mh][q][0];
            G[ks][row][col + 1] = c[mh][q][1];
            G[ks][row + 8][col] = c[mh][q][2];
            G[ks][row + 8][col + 1] = c[mh][q][3];
        }
}
__device__ __forceinline__ float gsum(float (*G)[32][33], int row, int b) {
    float s = 0.f;
#pragma unroll
    for (int k = 0; k < 8; k++) s += G[k][row][b];
    return s;
}

// ---------------- persistent decode loop: 512 threads, 4 phases/step ----------------
__global__ void __launch_bounds__(512, 1)
decode_loop(const int* __restrict__ tok, const float* __restrict__ Eb,
            const float* __restrict__ bk, const float* __restrict__ bc) {
    __shared__ __align__(16) float Gs[8][32][33];
    int bid = blockIdx.x, tid = threadIdx.x;
    int b = tid & 31;
    int e = 0;
    const uint4* W0t = dW0p + (size_t)bid * (80 * 64);
    const uint4* W1t = dW1p + (size_t)bid * (64 * 64);

    for (int t = 0; t < T_; t++) {
        int cur = t & 1, nxt = cur ^ 1;

        // ---- Phase A: layer-0 fp8 GEMM + LSTM pointwise ----
        gemm_p8<K0_>(W0t, dX0p[cur], Gs);
        __syncthreads();
        if (tid < 256) {
            int hl = tid >> 5;
            int h = bid * 8 + hl, j0 = bid * 32 + hl * 4;
            float g0 = gsum(Gs, hl * 4 + 0, b) + dB0[j0 + 0];
            float g1 = gsum(Gs, hl * 4 + 1, b) + dB0[j0 + 1];
            float g2 = gsum(Gs, hl * 4 + 2, b) + dB0[j0 + 2];
            float g3 = gsum(Gs, hl * 4 + 3, b) + dB0[j0 + 3];
            float c = dC0[h * 32 + b];
            float cn = fsig(g1) * c + fsig(g0) * ftanh(g2);
            float hn = fsig(g3) * ftanh(cn);
            dC0[h * 32 + b] = cn;
            unsigned char h8 = f2e4m3(hn);
            ((unsigned char*)&dX1p[cur][0])[xpk8(b, h)] = h8;
            ((unsigned char*)&dX0p[nxt][0])[xpk8(b, 1536 + h)] = h8;
        }
        gbar(++e);

        // ---- Phase B: layer-1 fp8 GEMM + LSTM pointwise ----
        gemm_p8<K1_>(W1t, dX1p[cur], Gs);
        __syncthreads();
        if (tid < 256) {
            int hl = tid >> 5;
            int h = bid * 8 + hl, j0 = bid * 32 + hl * 4;
            float g0 = gsum(Gs, hl * 4 + 0, b) + dB1[j0 + 0];
            float g1 = gsum(Gs, hl * 4 + 1, b) + dB1[j0 + 1];
            float g2 = gsum(Gs, hl * 4 + 2, b) + dB1[j0 + 2];
            float g3 = gsum(Gs, hl * 4 + 3, b) + dB1[j0 + 3];
            float c = dC1[h * 32 + b];
            float cn = fsig(g1) * c + fsig(g0) * ftanh(g2);
            float hn = fsig(g3) * ftanh(cn);
            dC1[h * 32 + b] = cn;
            ((__nv_bfloat16*)dXcp)[xpk(b, h)] = __float2bfloat16(hn);   // htop (bf16, phase C)
            ((unsigned char*)&dX1p[nxt][0])[xpk8(b, 1024 + h)] = f2e4m3(hn);
            dHBh[((size_t)t * 32 + b) * H_ + h] = __float2bfloat16(hn);
        }
        gbar(++e);

        // ---- Phase C: q/M/comb1 bf16 GEMMs + emb prefetch ----
        if (bid < 32) {
            gemm_p<H_>(dWkp + (size_t)bid * 4096, dXcp, Gs);
            __syncthreads();
            int rl = tid >> 5;
            dQ[(bid * 32 + rl) * 32 + b] = gsum(Gs, rl, b);
            dQ[(bid * 32 + rl + 16) * 32 + b] = gsum(Gs, rl + 16, b);
        } else if (bid < 64) {
            int jt = bid - 32;
            gemm_p<H_>(dWc2p + (size_t)jt * 4096, dXcp, Gs);
            __syncthreads();
            int rl = tid >> 5;
            dM[((size_t)b * H_ + jt * 32 + rl) * T_ + t] = gsum(Gs, rl, b);
            dM[((size_t)b * H_ + jt * 32 + rl + 16) * T_ + t] = gsum(Gs, rl + 16, b);
        } else if (bid < 96) {
            int jt = bid - 64;
            gemm_p<H_>(dWc1p + (size_t)jt * 4096, dXcp, Gs);
            __syncthreads();
            int rl = tid >> 5;
            dCb1[(jt * 32 + rl) * 32 + b] = gsum(Gs, rl, b);
            dCb1[(jt * 32 + rl + 16) * 32 + b] = gsum(Gs, rl + 16, b);
        } else if (t + 1 < T_) {
            int bb = bid - 96;
            int tk = tok[(t + 1) * 32 + bb];
            ((unsigned char*)&dX0p[nxt][0])[xpk8(bb, tid)] =
                f2e4m3(ldcgf(&Eb[(size_t)tk * 512 + tid]));
        }
        gbar(++e);

        // ---- Phase D: attention + comb finalize (32 blocks, 512 threads) ----
        if (bid < 32) {
            int bb = bid;
            float* qv = (float*)Gs;          // 1024
            float* sc = qv + 1024;           // 64
            float* red = sc + 64;            // 512
            int h2 = tid * 2;
            {
                qv[h2] = ldcgf(&dQ[h2 * 32 + bb]);
                qv[h2 + 1] = ldcgf(&dQ[(h2 + 1) * 32 + bb]);
                const __nv_bfloat16* ht = &dHBh[((size_t)t * 32 + bb) * H_ + h2];
                red[tid] = __bfloat162float(ht[0]) * bk[h2]
                         + __bfloat162float(ht[1]) * bk[h2 + 1];
            }
            __syncthreads();
            for (int st = 256; st; st >>= 1) { if (tid < st) red[tid] += red[tid + st]; __syncthreads(); }
            float bkh = red[0];
            __syncthreads();
            int w = tid >> 5, lane = tid & 31;
            for (int si = w; si <= t; si += 16) {
                const __nv_bfloat16* hr = &dHBh[((size_t)si * 32 + bb) * H_];
                float acc = 0.f;
                for (int h = lane * 8; h < H_; h += 256) {
                    uint4 hv = *(const uint4*)(hr + h);
                    float2 a0 = __bfloat1622float2(*(__nv_bfloat162*)&hv.x);
                    float2 a1 = __bfloat1622float2(*(__nv_bfloat162*)&hv.y);
                    float2 a2 = __bfloat1622float2(*(__nv_bfloat162*)&hv.z);
                    float2 a3 = __bfloat1622float2(*(__nv_bfloat162*)&hv.w);
                    acc += a0.x * qv[h] + a0.y * qv[h + 1] + a1.x * qv[h + 2] + a1.y * qv[h + 3]
                         + a2.x * qv[h + 4] + a2.y * qv[h + 5] + a3.x * qv[h + 6] + a3.y * qv[h + 7];
                }
#pragma unroll
                for (int o = 16; o; o >>= 1) acc += __shfl_xor_sync(0xffffffffu, acc, o);
                if (!lane) {
                    float v = acc + bkh;
                    if (tok[si * 32 + bb] == 0) v += -99999.0f;
                    sc[si] = v;
                }
            }
            __syncthreads();
            float v = (tid < 64 && tid <= t) ? sc[tid] : -1e30f;
            red[tid] = v; __syncthreads();
            for (int st = 256; st; st >>= 1) { if (tid < st) red[tid] = fmaxf(red[tid], red[tid + st]); __syncthreads(); }
            float m = red[0]; __syncthreads();
            float ev = (tid < 64 && tid <= t) ? fexp(v - m) : 0.f;
            red[tid] = ev; __syncthreads();
            for (int st = 256; st; st >>= 1) { if (tid < st) red[tid] += red[tid + st]; __syncthreads(); }
            float inv = 1.0f / red[0];
            if (tid < 64) sc[tid] = (tid <= t) ? ev * inv : 0.f;
            __syncthreads();
            if (tid < 64) dDist[(t * T_ + tid) * 32 + bb] = sc[tid];
            {
                int j = tid * 2;
                float a0 = ldcgf(&dCb1[(j + 0) * 32 + bb]);
                float a1 = ldcgf(&dCb1[(j + 1) * 32 + bb]);
                const float* M0 = &dM[((size_t)bb * H_ + j) * T_];
                const float* M1 = M0 + T_;
                for (int s4 = 0; s4 <= t; s4 += 4) {
                    uint4 u0 = ldcg4(M0 + s4);
                    uint4 u1 = ldcg4(M1 + s4);
                    float4 m0 = *(float4*)&u0;
                    float4 m1 = *(float4*)&u1;
                    float d0 = sc[s4], d1 = sc[s4 + 1], d2 = sc[s4 + 2], d3 = sc[s4 + 3];
                    a0 = fmaf(d0, m0.x, a0); a1 = fmaf(d0, m1.x, a1);
                    a0 = fmaf(d1, m0.y, a0); a1 = fmaf(d1, m1.y, a1);
                    a0 = fmaf(d2, m0.z, a0); a1 = fmaf(d2, m1.z, a1);
                    a0 = fmaf(d3, m0.w, a0); a1 = fmaf(d3, m1.w, a1);
                }
                a0 += bc[j]; a1 += bc[j + 1];
                // feed (fp8, 2 adjacent bytes) + A matrix (bf16)
                unsigned short f2 = (unsigned short)f2e4m3(a0)
                                  | ((unsigned short)f2e4m3(a1) << 8);
                ((unsigned short*)&dX0p[nxt][0])[xpk8(bb, 512 + j) >> 1] = f2;
                __nv_bfloat162 p0 = __floats2bfloat162_rn(a0, a1);
                *(unsigned*)&dA[((size_t)t * 32 + bb) * H_ + j] = *(unsigned*)&p0;
            }
        }
        gbar(++e);
    }
}

// ---------------- prep kernel 0: pack W0 + W1 (fp8) ----------------
__global__ void pk_big(const float* __restrict__ Wih0, const float* __restrict__ Whh0,
                       const float* __restrict__ Wih1, const float* __restrict__ Whh1) {
    const size_t N0 = (size_t)4096 * K0_ / 16;
    const size_t N1 = (size_t)4096 * K1_ / 16;
    for (size_t uu = (size_t)blockIdx.x * blockDim.x + threadIdx.x; uu < N0 + N1;
         uu += (size_t)gridDim.x * blockDim.x) {
        bool first = uu < N0;
        size_t u = first ? uu : uu - N0;
        int PAN = first ? 80 : 64;                 // k32 panels per row-tile
        const float* Wih = first ? Wih0 : Wih1;
        const float* Whh = first ? Whh0 : Whh1;
        int KIH = first ? 1536 : 1024;
        int lane = (int)(u & 31); size_t t1 = u >> 5; int mh = (int)(t1 & 1); size_t t2 = t1 >> 1;
        int p = (int)(t2 % PAN); int jt = (int)(t2 / PAN);
        int r = lane >> 2, ci = lane & 3;
        unsigned o[4];
#pragma unroll
        for (int reg = 0; reg < 4; reg++) {
            int rh = reg & 1, hi = reg >> 1;
            int row = jt * 32 + mh * 16 + rh * 8 + r;
            int orow = (row & 3) * 1024 + (row >> 2);   // gate-interleave
            int kb = p * 32 + hi * 16 + ci * 4;
            unsigned wv = 0;
#pragma unroll
            for (int lo = 0; lo < 4; lo++) {
                int k = kb + lo;
                float v = (k < KIH) ? Wih[(size_t)orow * KIH + k]
                                    : Whh[(size_t)orow * 1024 + (k - KIH)];
                wv |= (unsigned)(unsigned char)__nv_cvt_float_to_fp8(v, __NV_SATFINITE, __NV_E4M3)
                      << (lo * 8);
            }
            o[reg] = wv;
        }
        if (first) dW0p[u] = make_uint4(o[0], o[1], o[2], o[3]);
        else dW1p[u] = make_uint4(o[0], o[1], o[2], o[3]);
    }
}

// ---------------- prep kernel 1: pack Wk^T/Wc1/Wc2 (bf16) + cast Wp ----------------
__global__ void pk_small(const float* __restrict__ Wk, const float* __restrict__ Wc,
                         const float* __restrict__ Wp) {
    const size_t NP = (size_t)H_ * H_ / 8;
    const size_t NW = (size_t)V_ * H_ / 8;
    for (size_t uu = (size_t)blockIdx.x * blockDim.x + threadIdx.x; uu < 3 * NP + NW;
         uu += (size_t)gridDim.x * blockDim.x) {
        if (uu < 3 * NP) {
            int which = (int)(uu / NP);
            size_t rem = uu % NP;
            int lane = (int)(rem & 31); size_t t1 = rem >> 5; int mh = (int)(t1 & 1); size_t t2 = t1 >> 1;
            int p = (int)(t2 % 64); int jt = (int)(t2 / 64);
            int r = lane >> 2, ci = lane & 3;
            unsigned o[4];
#pragma unroll
            for (int reg = 0; reg < 4; reg++) {
                int rh = reg & 1, hi = reg >> 1;
                int row = jt * 32 + mh * 16 + rh * 8 + r;
                int col = p * 16 + hi * 8 + ci * 2;
                float v0, v1;
                if (which == 0) { v0 = Wk[(size_t)col * 1024 + row]; v1 = Wk[(size_t)(col + 1) * 1024 + row]; }
                else if (which == 1) { v0 = Wc[(size_t)row * 2048 + col]; v1 = Wc[(size_t)row * 2048 + col + 1]; }
                else { v0 = Wc[(size_t)row * 2048 + 1024 + col]; v1 = Wc[(size_t)row * 2048 + 1025 + col]; }
                __nv_bfloat162 bb = __floats2bfloat162_rn(v0, v1);
                o[reg] = *(unsigned*)&bb;
            }
            if (which == 0) dWkp[rem] = make_uint4(o[0], o[1], o[2], o[3]);
            else if (which == 1) dWc1p[rem] = make_uint4(o[0], o[1], o[2], o[3]);
            else dWc2p[rem] = make_uint4(o[0], o[1], o[2], o[3]);
        } else {
            size_t w = uu - 3 * NP;
            float4 f0 = *(const float4*)(Wp + w * 8);
            float4 f1 = *(const float4*)(Wp + w * 8 + 4);
            __nv_bfloat162 b0 = __floats2bfloat162_rn(f0.x, f0.y);
            __nv_bfloat162 b1 = __floats2bfloat162_rn(f0.z, f0.w);
            __nv_bfloat162 b2 = __floats2bfloat162_rn(f1.x, f1.y);
            __nv_bfloat162 b3 = __floats2bfloat162_rn(f1.z, f1.w);
            ((uint4*)dWp)[w] = make_uint4(*(unsigned*)&b0, *(unsigned*)&b1,
                                          *(unsigned*)&b2, *(unsigned*)&b3);
        }
    }
}

// ---------------- prep kernel 2: state init ----------------
__global__ void pk_state(const float* __restrict__ bih0, const float* __restrict__ bhh0,
                         const float* __restrict__ bih1, const float* __restrict__ bhh1,
                         const float* __restrict__ h0, const float* __restrict__ c0,
                         const float* __restrict__ Eb, const int* __restrict__ tok) {
    int i = blockIdx.x * blockDim.x + threadIdx.x;   // 32768 threads
    int bb = i >> 10, h = i & 1023;
    dC0[h * 32 + bb] = c0[(size_t)bb * H_ + h];
    dC1[h * 32 + bb] = c0[(size_t)B_ * H_ + (size_t)bb * H_ + h];
    unsigned char* X0 = (unsigned char*)&dX0p[0][0];
    unsigned char* X1 = (unsigned char*)&dX1p[0][0];
    X0[xpk8(bb, 1536 + h)] =
        (unsigned char)__nv_cvt_float_to_fp8(h0[(size_t)bb * H_ + h], __NV_SATFINITE, __NV_E4M3);
    X1[xpk8(bb, 1024 + h)] =
        (unsigned char)__nv_cvt_float_to_fp8(h0[(size_t)B_ * H_ + (size_t)bb * H_ + h],
                                             __NV_SATFINITE, __NV_E4M3);
    X0[xpk8(bb, 512 + h)] = 0;                       // feed = 0 (e4m3 zero = 0x00)
    if (i < 4096) {
        int h2 = i >> 2, g = i & 3;
        dB0[i] = bih0[g * 1024 + h2] + bhh0[g * 1024 + h2];
        dB1[i] = bih1[g * 1024 + h2] + bhh1[g * 1024 + h2];
    }
    if (i < 32 * 512) {
        int b2 = i >> 9, e2 = i & 511;
        X0[xpk8(b2, e2)] =
            (unsigned char)__nv_cvt_float_to_fp8(Eb[(size_t)tok[b2] * 512 + e2],
                                                 __NV_SATFINITE, __NV_E4M3);
    }
    if (i == 0) { gCnt = 0; gRel = 0; }
}

// ---------------- logits GEMM: 128x128 double-buffered bf16 ----------------
__global__ void __launch_bounds__(256) gemm_logits(const float* __restrict__ bp) {
    int v0 = blockIdx.x * 128, r0 = blockIdx.y * 128;
    __shared__ __nv_bfloat16 As[2][128][24];
    __shared__ __nv_bfloat16 Bs[2][128][24];
    int tid = threadIdx.x, wid = tid >> 5, lane = tid & 31;
    int mh = wid >> 2, nq = wid & 3;
    int r = lane >> 2, c2 = (lane & 3) * 2;
    int lrow = tid >> 1, lseg = (tid & 1) * 8;
    float acc[4][4][4];
#pragma unroll
    for (int a = 0; a < 4; a++)
#pragma unroll
        for (int bb = 0; bb < 4; bb++)
#pragma unroll
            for (int c = 0; c < 4; c++) acc[a][bb][c] = 0.f;

    *(uint4*)&As[0][lrow][lseg] = *(const uint4*)&dA[(size_t)(r0 + lrow) * H_ + lseg];
    *(uint4*)&Bs[0][lrow][lseg] = *(const uint4*)&dWp[(size_t)(v0 + lrow) * H_ + lseg];
    for (int ks = 0; ks < 64; ks++) {
        __syncthreads();
        uint4 na, nb;
        if (ks < 63) {
            na = *(const uint4*)&dA[(size_t)(r0 + lrow) * H_ + (ks + 1) * 16 + lseg];
            nb = *(const uint4*)&dWp[(size_t)(v0 + lrow) * H_ + (ks + 1) * 16 + lseg];
        }
        int cur = ks & 1;
#pragma unroll
        for (int mi = 0; mi < 4; mi++) {
            int row = mh * 64 + mi * 16;
            unsigned a0 = *(unsigned*)&As[cur][row + r][c2];
            unsigned a1 = *(unsigned*)&As[cur][row + r + 8][c2];
            unsigned a2 = *(unsigned*)&As[cur][row + r][c2 + 8];
            unsigned a3 = *(unsigned*)&As[cur][row + r + 8][c2 + 8];
#pragma unroll
            for (int ni = 0; ni < 4; ni++) {
                int n = nq * 32 + ni * 8 + r;
                unsigned b0 = *(unsigned*)&Bs[cur][n][c2];
                unsigned b1 = *(unsigned*)&Bs[cur][n][c2 + 8];
                mma16(acc[mi][ni], a0, a1, a2, a3, b0, b1);
            }
        }
        if (ks < 63) {
            *(uint4*)&As[cur ^ 1][lrow][lseg] = na;
            *(uint4*)&Bs[cur ^ 1][lrow][lseg] = nb;
        }
    }
#pragma unroll
    for (int mi = 0; mi < 4; mi++) {
        int row = r0 + mh * 64 + mi * 16 + r;
#pragma unroll
        for (int ni = 0; ni < 4; ni++) {
            int col = v0 + nq * 32 + ni * 8 + c2;
            float b0 = bp[col], b1 = bp[col + 1];
            dLog[(size_t)row * V_ + col] = acc[mi][ni][0] + b0;
            dLog[(size_t)row * V_ + col + 1] = acc[mi][ni][1] + b1;
            dLog[(size_t)(row + 8) * V_ + col] = acc[mi][ni][2] + b0;
            dLog[(size_t)(row + 8) * V_ + col + 1] = acc[mi][ni][3] + b1;
        }
    }
}

// ---------------- softmax + mixture log output ----------------
__global__ void softmax_out(float* __restrict__ out) {
    int rr = blockIdx.x, tid = threadIdx.x;
    const float* L = dLog + (size_t)rr * V_;
    __shared__ float rm[256], rs[256];
    float m = -1e30f, s = 0.f;
    for (int v = tid; v < V_; v += 256) {
        float x = L[v];
        if (x > m) { s = fmaf(s, fexp(m - x), 1.0f); m = x; }
        else s += fexp(x - m);
    }
    rm[tid] = m; rs[tid] = s; __syncthreads();
    for (int st = 128; st; st >>= 1) {
        if (tid < st) {
            float m2 = rm[tid + st], s2 = rs[tid + st];
            float M = fmaxf(rm[tid], m2);
            rs[tid] = rs[tid] * fexp(rm[tid] - M) + s2 * fexp(m2 - M);
            rm[tid] = M;
        }
        __syncthreads();
    }
    m = rm[0];
    float inv = 1.0f / rs[0];
    float cw = fexp(L[3] - m) * inv;          // COPY_ID = 3
    if (tid == 0) { dMx[rr] = m; dIs[rr] = inv; dCw[rr] = cw; }
    float ce = cw * 1e-7f, oc = (1.0f - cw) * inv;
    float* O = out + (size_t)rr * V_;
    for (int v = tid; v < V_; v += 256)
        O[v] = flog(fmaf(oc, fexp(L[v] - m), ce));
}

__global__ void fixup(float* __restrict__ out, const int* __restrict__ tok) {
    int rr = blockIdx.x;
    int t = rr >> 5, b = rr & 31;
    int s = threadIdx.x;
    __shared__ int tk[T_];
    __shared__ float dd[T_];
    tk[s] = tok[s * 32 + b];
    dd[s] = dDist[(t * T_ + s) * 32 + b];
    __syncthreads();
    int mytok = tk[s];
    float tot = 0.f;
    for (int s2 = 0; s2 < T_; s2++) if (tk[s2] == mytok) tot += dd[s2];
    float m = dMx[rr], inv = dIs[rr], cw = dCw[rr];
    float p = fexp(dLog[(size_t)rr * V_ + mytok] - m) * inv;
    out[(size_t)rr * V_ + mytok] = flog(cw * (1e-7f + tot) + (1.0f - cw) * p);
}

// ---------------- host ----------------
extern "C" void kernel_launch(void* const* d_in, const int* in_sizes, int n_in,
                              void* d_out, int out_size) {
    const int* tok = (const int*)d_in[0];
    const float* h0 = (const float*)d_in[1];
    const float* c0 = (const float*)d_in[2];
    const float* Eb = (const float*)d_in[3];
    const float* Wih0 = (const float*)d_in[4];
    const float* Whh0 = (const float*)d_in[5];
    const float* bih0 = (const float*)d_in[6];
    const float* bhh0 = (const float*)d_in[7];
    const float* Wih1 = (const float*)d_in[8];
    const float* Whh1 = (const float*)d_in[9];
    const float* bih1 = (const float*)d_in[10];
    const float* bhh1 = (const float*)d_in[11];
    const float* Wk = (const float*)d_in[12];
    const float* bk = (const float*)d_in[13];
    const float* Wc = (const float*)d_in[14];
    const float* bc = (const float*)d_in[15];
    const float* Wp = (const float*)d_in[16];
    const float* bp = (const float*)d_in[17];
    float* out = (float*)d_out;

    pk_big<<<4096, 256>>>(Wih0, Whh0, Wih1, Whh1);           // launch 0
    pk_small<<<4096, 256>>>(Wk, Wc, Wp);                     // launch 1
    pk_state<<<128, 256>>>(bih0, bhh0, bih1, bhh1, h0, c0, Eb, tok);  // launch 2
    decode_loop<<<NBLK, 512>>>(tok, Eb, bk, bc);             // launch 3 (profiled)
    gemm_logits<<<dim3(V_ / 128, (T_ * B_) / 128), 256>>>(bp);
    softmax_out<<<T_ * B_, 256>>>(out);
    fixup<<<T_ * B_, 64>>>(out, tok);
}